// round 12
// baseline (speedup 1.0000x reference)
#include <cuda_runtime.h>
#include <cuda_bf16.h>
#include <math.h>
#include <cstdint>

#define S_LEN 2048
#define DH    64
#define NELEM (2 * 16 * 2048 * 64)
#define LOG2E 1.4426950408889634f

// bf16 hi/lo scratch: Q (pre-scaled by log2e), K rope'd; V plain. [bh][s][d].
__device__ __align__(16) __nv_bfloat16 g_Qhi[NELEM], g_Qlo[NELEM];
__device__ __align__(16) __nv_bfloat16 g_Khi[NELEM], g_Klo[NELEM];
__device__ __align__(16) __nv_bfloat16 g_Vhi[NELEM], g_Vlo[NELEM];

// ---------------------------------------------------------------------------
// helpers
// ---------------------------------------------------------------------------
__device__ __forceinline__ uint32_t smem_u32(const void* p) {
    uint32_t a;
    asm("{ .reg .u64 t; cvta.to.shared.u64 t, %1; cvt.u32.u64 %0, t; }" : "=r"(a) : "l"(p));
    return a;
}
__device__ __forceinline__ void cp16(uint32_t dst, const void* src) {
    asm volatile("cp.async.cg.shared.global [%0], [%1], 16;" :: "r"(dst), "l"(src));
}
__device__ __forceinline__ void cp_commit() { asm volatile("cp.async.commit_group;"); }
template <int N>
__device__ __forceinline__ void cp_wait() { asm volatile("cp.async.wait_group %0;" :: "n"(N)); }

__device__ __forceinline__ void ldsm4(uint32_t r[4], uint32_t a) {
    asm volatile("ldmatrix.sync.aligned.m8n8.x4.shared.b16 {%0,%1,%2,%3}, [%4];"
                 : "=r"(r[0]), "=r"(r[1]), "=r"(r[2]), "=r"(r[3]) : "r"(a));
}
__device__ __forceinline__ void ldsm4t(uint32_t r[4], uint32_t a) {
    asm volatile("ldmatrix.sync.aligned.m8n8.x4.trans.shared.b16 {%0,%1,%2,%3}, [%4];"
                 : "=r"(r[0]), "=r"(r[1]), "=r"(r[2]), "=r"(r[3]) : "r"(a));
}
// non-volatile: ptxas may schedule freely (register-only effects)
__device__ __forceinline__ void mma_bf16(float c[4], const uint32_t a[4],
                                         uint32_t b0, uint32_t b1) {
    asm("mma.sync.aligned.m16n8k16.row.col.f32.bf16.bf16.f32 "
        "{%0,%1,%2,%3}, {%4,%5,%6,%7}, {%8,%9}, {%0,%1,%2,%3};"
        : "+f"(c[0]), "+f"(c[1]), "+f"(c[2]), "+f"(c[3])
        : "r"(a[0]), "r"(a[1]), "r"(a[2]), "r"(a[3]), "r"(b0), "r"(b1));
}
__device__ __forceinline__ float ex2(float x) {
    float y;
    asm("ex2.approx.f32 %0, %1;" : "=f"(y) : "f"(x));
    return y;
}
// packed bf16x2 convert: result = {lo16 = bf16(a), hi16 = bf16(b)}
__device__ __forceinline__ uint32_t cvt_bf2(float a, float b) {
    uint32_t r;
    asm("cvt.rn.bf16x2.f32 %0, %1, %2;" : "=r"(r) : "f"(b), "f"(a));
    return r;
}
// hi/lo split of a pair in 6 instructions
__device__ __forceinline__ void pack_pair(float a, float b, uint32_t& hi, uint32_t& lo) {
    hi = cvt_bf2(a, b);
    float ha = __uint_as_float(hi << 16);
    float hb = __uint_as_float(hi & 0xFFFF0000u);
    lo = cvt_bf2(a - ha, b - hb);
}

// ---------------------------------------------------------------------------
// Fused prep: RoPE+split Q (x log2e), K; split V. One thread per (even,odd).
// ---------------------------------------------------------------------------
__global__ void prep_kernel(const float* __restrict__ Q, const float* __restrict__ K,
                            const float* __restrict__ V, int pairs) {
    int idx = blockIdx.x * blockDim.x + threadIdx.x;
    if (idx >= pairs) return;
    int i = idx & 31, bhs = idx >> 5, s = bhs & (S_LEN - 1);
    float div = expf((float)(2 * i) * (-logf(10000.0f) / (float)DH));
    float sn, cs;
    sincosf((float)s * div, &sn, &cs);
    size_t base = (size_t)bhs * DH + 2 * i;

    float qe = Q[base], qo = Q[base + 1];
    float q0 = (qe * cs - qo * sn) * LOG2E;
    float q1 = (qe * sn + qo * cs) * LOG2E;
    uint32_t h, l;
    pack_pair(q0, q1, h, l);
    *(uint32_t*)&g_Qhi[base] = h;
    *(uint32_t*)&g_Qlo[base] = l;

    float ke = K[base], ko = K[base + 1];
    float k0 = ke * cs - ko * sn, k1 = ke * sn + ko * cs;
    pack_pair(k0, k1, h, l);
    *(uint32_t*)&g_Khi[base] = h;
    *(uint32_t*)&g_Klo[base] = l;

    float2 v = *(const float2*)&V[base];
    pack_pair(v.x, v.y, h, l);
    *(uint32_t*)&g_Vhi[base] = h;
    *(uint32_t*)&g_Vlo[base] = l;
}

// ---------------------------------------------------------------------------
// Flash attention, mma.sync bf16x3, no-rescale softmax (exp2-domain scores).
// Grid (16, 32). 256 threads. Cross-stage pipeline: softmax(jp) -> QK(jp+1)
// -> PV(jp) fills softmax latency with MMA issue. Fully-masked tiles skipped.
// ---------------------------------------------------------------------------
#define SM_QHI   0
#define SM_QLO   16384
#define SM_KV    32768
#define KVBUF    32768
#define SM_BYTES 98304

__global__ __launch_bounds__(256, 2) void attn_kernel(float* __restrict__ O) {
    extern __shared__ __align__(1024) char smem[];
    const uint32_t sb = smem_u32(smem);
    const int tid  = threadIdx.x;
    const int lane = tid & 31;
    const int warp = tid >> 5;
    const int mr   = warp * 16;
    const int qt   = 15 - blockIdx.x;
    const int bh   = blockIdx.y;
    const size_t hoff = (size_t)bh * S_LEN * DH;
    const int ntiles = 2 * qt + 2;

    // ---- streamlined KV staging: thread owns one array, 8 chunks @ stride 1024
    const int a64 = tid >> 6, t64 = tid & 63;
    const char* kv_src = (const char*)((a64 == 0) ? (const void*)(g_Khi + hoff)
                        : (a64 == 1) ? (const void*)(g_Klo + hoff)
                        : (a64 == 2) ? (const void*)(g_Vhi + hoff)
                                     : (const void*)(g_Vlo + hoff))
                        + t64 * 16;
    const uint32_t kv_dst = sb + SM_KV +
        (uint32_t)(a64 * 8192 + (t64 >> 3) * 128 + (((t64 & 7) << 4) ^ ((t64 >> 3) << 4)));

    // group A: Q tiles (2048 x 16B)
    {
        const char* gQh = (const char*)(g_Qhi + hoff + (size_t)qt * 128 * DH);
        const char* gQl = (const char*)(g_Qlo + hoff + (size_t)qt * 128 * DH);
#pragma unroll
        for (int t = 0; t < 8; t++) {
            int i = tid + t * 256;
            int arr = i >> 10, idx = i & 1023;
            int r = idx >> 3, cs = (idx & 7) << 4;
            const char* g = arr ? gQl : gQh;
            cp16(sb + SM_QHI + arr * 16384 + r * 128 + (cs ^ ((r & 7) << 4)),
                 g + r * 128 + cs);
        }
        cp_commit();
    }
    // group B: KV tile 0
    {
#pragma unroll
        for (int j = 0; j < 8; j++)
            cp16(kv_dst + (uint32_t)(j * 1024), kv_src + j * 1024);
        cp_commit();
    }

    // ---- per-lane ldmatrix address components ----
    const int ar  = mr + (lane & 15);
    const int acs = ((lane >> 4) & 1) << 4;
    const uint32_t asw = (ar & 7) << 4;
    const int ki = lane >> 3, kr = lane & 7;
    const uint32_t krow_off  = (uint32_t)(((ki >> 1) * 8 + kr) * 128);
    const uint32_t khalf_sel = (uint32_t)((ki & 1) << 4);
    const uint32_t krsw      = (uint32_t)(kr << 4);
    const int vi = lane >> 3, vr = lane & 7;
    const uint32_t vrow_off = (uint32_t)(((vi & 1) * 8 + vr) * 128);
    const uint32_t vdsel    = (uint32_t)(vi >> 1);
    const uint32_t vrsw     = (uint32_t)(vr << 4);

    cp_wait<1>();          // Q (group A) complete
    __syncthreads();

    // hoist Q hi+lo fragments (loop-invariant)
    uint32_t qh[4][4], ql[4][4];
    {
        const uint32_t qhi_row = sb + SM_QHI + ar * 128;
        const uint32_t qlo_row = sb + SM_QLO + ar * 128;
#pragma unroll
        for (int kc = 0; kc < 4; kc++) {
            const uint32_t aoff = (uint32_t)(((kc << 5) | acs) ^ asw);
            ldsm4(qh[kc], qhi_row + aoff);
            ldsm4(ql[kc], qlo_row + aoff);
        }
    }

    float o[8][4];
#pragma unroll
    for (int j = 0; j < 8; j++)
#pragma unroll
        for (int e = 0; e < 4; e++) o[j][e] = 0.0f;
    float lsum0 = 0.0f, lsum1 = 0.0f;

    const int r0g = qt * 128 + mr + (lane >> 2);
    const int cb0 = 2 * (lane & 3);

    for (int it = 0; it < ntiles; it++) {
        if (it + 1 < ntiles) {
            const uint32_t nb = kv_dst + (uint32_t)((it + 1) & 1) * KVBUF;
            const char* src = kv_src + (size_t)(it + 1) * 8192;
#pragma unroll
            for (int j = 0; j < 8; j++)
                cp16(nb + (uint32_t)(j * 1024), src + j * 1024);
            cp_commit();
            cp_wait<1>();
        } else {
            cp_wait<0>();
        }
        __syncthreads();

        // fully-masked tile for this warp? (min k of tile > max row of warp)
        if (it * 64 <= qt * 128 + mr + 15) {
            const uint32_t kvb = sb + SM_KV + (uint32_t)(it & 1) * KVBUF;
            const uint32_t sKh = kvb, sKl = kvb + 8192, sVh = kvb + 16384, sVl = kvb + 24576;

            const int kb0 = it * 64 + cb0;
            const bool unmasked = (it * 64 + 63 <= qt * 128 + mr);   // warp-uniform

            // QK for one n-pair jp -> c0/c1
            auto qk = [&](int jp, float (&c0)[4], float (&c1)[4]) {
#pragma unroll
                for (int e = 0; e < 4; e++) { c0[e] = 0.f; c1[e] = 0.f; }
                const uint32_t kbase = (uint32_t)(jp << 11) + krow_off;
#pragma unroll
                for (int kc = 0; kc < 4; kc++) {
                    uint32_t k4h[4], k4l[4];
                    const uint32_t kb_ = kbase + ((((uint32_t)(kc << 5)) | khalf_sel) ^ krsw);
                    ldsm4(k4h, sKh + kb_);
                    ldsm4(k4l, sKl + kb_);
                    mma_bf16(c0, qh[kc], k4h[0], k4h[1]);
                    mma_bf16(c1, qh[kc], k4h[2], k4h[3]);
                    mma_bf16(c0, qh[kc], k4l[0], k4l[1]);
                    mma_bf16(c1, qh[kc], k4l[2], k4l[3]);
                    mma_bf16(c0, ql[kc], k4h[0], k4h[1]);
                    mma_bf16(c1, ql[kc], k4h[2], k4h[3]);
                }
            };

            uint32_t Ah[4], Al[4];
            // softmax of jp's scores into Ah/Al (+ lsum)
            auto softmax_jp = [&](int jp, const float (&c0)[4], const float (&c1)[4]) {
                float e0, e1, e2, e3, f0, f1, f2, f3;
                if (unmasked) {
                    e0 = ex2(c0[0]); e1 = ex2(c0[1]); e2 = ex2(c0[2]); e3 = ex2(c0[3]);
                    f0 = ex2(c1[0]); f1 = ex2(c1[1]); f2 = ex2(c1[2]); f3 = ex2(c1[3]);
                } else {
                    const int cj0 = kb0 + 16 * jp, cj1 = cj0 + 8;
                    e0 = (cj0     <= r0g)     ? ex2(c0[0]) : 0.0f;
                    e1 = (cj0 + 1 <= r0g)     ? ex2(c0[1]) : 0.0f;
                    e2 = (cj0     <= r0g + 8) ? ex2(c0[2]) : 0.0f;
                    e3 = (cj0 + 1 <= r0g + 8) ? ex2(c0[3]) : 0.0f;
                    f0 = (cj1     <= r0g)     ? ex2(c1[0]) : 0.0f;
                    f1 = (cj1 + 1 <= r0g)     ? ex2(c1[1]) : 0.0f;
                    f2 = (cj1     <= r0g + 8) ? ex2(c1[2]) : 0.0f;
                    f3 = (cj1 + 1 <= r0g + 8) ? ex2(c1[3]) : 0.0f;
                }
                lsum0 += (e0 + e1) + (f0 + f1);
                lsum1 += (e2 + e3) + (f2 + f3);
                pack_pair(e0, e1, Ah[0], Al[0]);
                pack_pair(e2, e3, Ah[1], Al[1]);
                pack_pair(f0, f1, Ah[2], Al[2]);
                pack_pair(f2, f3, Ah[3], Al[3]);
            };

            // PV of jp's P chunk into all 8 d-tile accumulators
            auto pv_jp = [&](int jp) {
                const uint32_t vb_ = (uint32_t)(jp << 11) + vrow_off;
#pragma unroll
                for (int dp = 0; dp < 4; dp++) {
                    uint32_t v4h[4], v4l[4];
                    const uint32_t va = vb_ + ((((uint32_t)(2 * dp) + vdsel) << 4) ^ vrsw);
                    ldsm4t(v4h, sVh + va);
                    ldsm4t(v4l, sVl + va);
                    mma_bf16(o[2 * dp],     Ah, v4h[0], v4h[1]);
                    mma_bf16(o[2 * dp + 1], Ah, v4h[2], v4h[3]);
                    mma_bf16(o[2 * dp],     Ah, v4l[0], v4l[1]);
                    mma_bf16(o[2 * dp + 1], Ah, v4l[2], v4l[3]);
                    mma_bf16(o[2 * dp],     Al, v4h[0], v4h[1]);
                    mma_bf16(o[2 * dp + 1], Al, v4h[2], v4h[3]);
                }
            };

            // pipelined schedule: softmax(jp) ; QK(jp+1) ; PV(jp)
            float cA0[4], cA1[4], cB0[4], cB1[4];
            qk(0, cA0, cA1);
            softmax_jp(0, cA0, cA1);
            qk(1, cB0, cB1);
            pv_jp(0);
            softmax_jp(1, cB0, cB1);
            qk(2, cA0, cA1);
            pv_jp(1);
            softmax_jp(2, cA0, cA1);
            qk(3, cB0, cB1);
            pv_jp(2);
            softmax_jp(3, cB0, cB1);
            pv_jp(3);
        }
        __syncthreads();   // all warps done with this KV buffer
    }

    // ---- epilogue ----
    float l0 = lsum0, l1 = lsum1;
    l0 += __shfl_xor_sync(0xffffffffu, l0, 1);
    l0 += __shfl_xor_sync(0xffffffffu, l0, 2);
    l1 += __shfl_xor_sync(0xffffffffu, l1, 1);
    l1 += __shfl_xor_sync(0xffffffffu, l1, 2);
    const float inv0 = 1.0f / l0;
    const float inv1 = 1.0f / l1;
    float* ob0 = O + hoff + (size_t)r0g * DH;
    float* ob1 = ob0 + 8 * DH;
#pragma unroll
    for (int j = 0; j < 8; j++) {
        float2 w0 = {o[j][0] * inv0, o[j][1] * inv0};
        float2 w1 = {o[j][2] * inv1, o[j][3] * inv1};
        *(float2*)&ob0[j * 8 + cb0] = w0;
        *(float2*)&ob1[j * 8 + cb0] = w1;
    }
}

// ---------------------------------------------------------------------------
extern "C" void kernel_launch(void* const* d_in, const int* in_sizes, int n_in,
                              void* d_out, int out_size) {
    const float* Q = (const float*)d_in[0];
    const float* K = (const float*)d_in[1];
    const float* V = (const float*)d_in[2];
    float* O = (float*)d_out;

    int pairs = in_sizes[0] / 2;
    prep_kernel<<<(pairs + 255) / 256, 256>>>(Q, K, V, pairs);

    cudaFuncSetAttribute(attn_kernel, cudaFuncAttributeMaxDynamicSharedMemorySize, SM_BYTES);
    attn_kernel<<<dim3(16, 32), 256, SM_BYTES>>>(O);
}

// round 13
// speedup vs baseline: 1.0111x; 1.0111x over previous
#include <cuda_runtime.h>
#include <cuda_bf16.h>
#include <math.h>
#include <cstdint>

#define S_LEN 2048
#define DH    64
#define NELEM (2 * 16 * 2048 * 64)
#define LOG2E 1.4426950408889634f

// bf16 hi/lo scratch: Q (pre-scaled by log2e), K rope'd; V plain. [bh][s][d].
__device__ __align__(16) __nv_bfloat16 g_Qhi[NELEM], g_Qlo[NELEM];
__device__ __align__(16) __nv_bfloat16 g_Khi[NELEM], g_Klo[NELEM];
__device__ __align__(16) __nv_bfloat16 g_Vhi[NELEM], g_Vlo[NELEM];

// ---------------------------------------------------------------------------
// helpers
// ---------------------------------------------------------------------------
__device__ __forceinline__ uint32_t smem_u32(const void* p) {
    uint32_t a;
    asm("{ .reg .u64 t; cvta.to.shared.u64 t, %1; cvt.u32.u64 %0, t; }" : "=r"(a) : "l"(p));
    return a;
}
__device__ __forceinline__ void cp16(uint32_t dst, const void* src) {
    asm volatile("cp.async.cg.shared.global [%0], [%1], 16;" :: "r"(dst), "l"(src));
}
__device__ __forceinline__ void cp_commit() { asm volatile("cp.async.commit_group;"); }
template <int N>
__device__ __forceinline__ void cp_wait() { asm volatile("cp.async.wait_group %0;" :: "n"(N)); }

#define BAR_SYNC(id, cnt)   asm volatile("bar.sync %0, %1;"   :: "r"(id), "r"(cnt) : "memory")
#define BAR_ARRIVE(id, cnt) asm volatile("bar.arrive %0, %1;" :: "r"(id), "r"(cnt) : "memory")
// barrier ids: 1,2 = P-ready(parity), 3,4 = P-free(parity), 7,5 = QK group, 8,9 = PV group

__device__ __forceinline__ void ldsm4(uint32_t r[4], uint32_t a) {
    asm volatile("ldmatrix.sync.aligned.m8n8.x4.shared.b16 {%0,%1,%2,%3}, [%4];"
                 : "=r"(r[0]), "=r"(r[1]), "=r"(r[2]), "=r"(r[3]) : "r"(a));
}
__device__ __forceinline__ void ldsm4t(uint32_t r[4], uint32_t a) {
    asm volatile("ldmatrix.sync.aligned.m8n8.x4.trans.shared.b16 {%0,%1,%2,%3}, [%4];"
                 : "=r"(r[0]), "=r"(r[1]), "=r"(r[2]), "=r"(r[3]) : "r"(a));
}
__device__ __forceinline__ void mma_bf16(float c[4], const uint32_t a[4],
                                         uint32_t b0, uint32_t b1) {
    asm("mma.sync.aligned.m16n8k16.row.col.f32.bf16.bf16.f32 "
        "{%0,%1,%2,%3}, {%4,%5,%6,%7}, {%8,%9}, {%0,%1,%2,%3};"
        : "+f"(c[0]), "+f"(c[1]), "+f"(c[2]), "+f"(c[3])
        : "r"(a[0]), "r"(a[1]), "r"(a[2]), "r"(a[3]), "r"(b0), "r"(b1));
}
__device__ __forceinline__ float ex2(float x) {
    float y;
    asm("ex2.approx.f32 %0, %1;" : "=f"(y) : "f"(x));
    return y;
}
__device__ __forceinline__ uint32_t cvt_bf2(float a, float b) {
    uint32_t r;
    asm("cvt.rn.bf16x2.f32 %0, %1, %2;" : "=r"(r) : "f"(b), "f"(a));
    return r;
}
__device__ __forceinline__ void pack_pair(float a, float b, uint32_t& hi, uint32_t& lo) {
    hi = cvt_bf2(a, b);
    float ha = __uint_as_float(hi << 16);
    float hb = __uint_as_float(hi & 0xFFFF0000u);
    lo = cvt_bf2(a - ha, b - hb);
}

// ---------------------------------------------------------------------------
// Fused prep: RoPE+split Q (x log2e), K; split V. One thread per (even,odd).
// ---------------------------------------------------------------------------
__global__ void prep_kernel(const float* __restrict__ Q, const float* __restrict__ K,
                            const float* __restrict__ V, int pairs) {
    int idx = blockIdx.x * blockDim.x + threadIdx.x;
    if (idx >= pairs) return;
    int i = idx & 31, bhs = idx >> 5, s = bhs & (S_LEN - 1);
    float div = expf((float)(2 * i) * (-logf(10000.0f) / (float)DH));
    float sn, cs;
    sincosf((float)s * div, &sn, &cs);
    size_t base = (size_t)bhs * DH + 2 * i;

    float qe = Q[base], qo = Q[base + 1];
    float q0 = (qe * cs - qo * sn) * LOG2E;
    float q1 = (qe * sn + qo * cs) * LOG2E;
    uint32_t h, l;
    pack_pair(q0, q1, h, l);
    *(uint32_t*)&g_Qhi[base] = h;
    *(uint32_t*)&g_Qlo[base] = l;

    float ke = K[base], ko = K[base + 1];
    float k0 = ke * cs - ko * sn, k1 = ke * sn + ko * cs;
    pack_pair(k0, k1, h, l);
    *(uint32_t*)&g_Khi[base] = h;
    *(uint32_t*)&g_Klo[base] = l;

    float2 v = *(const float2*)&V[base];
    pack_pair(v.x, v.y, h, l);
    *(uint32_t*)&g_Vhi[base] = h;
    *(uint32_t*)&g_Vlo[base] = l;
}

// ---------------------------------------------------------------------------
// Warp-specialized flash attention. BM=64, BN=32. Grid (32, 32), 256 threads.
// Warps 0-3: QK+softmax -> P smem. Warps 4-7: PV from P smem. P double-buffered.
// K double-buffered (QK-owned cp.async); V triple-buffered (PV-owned).
// ---------------------------------------------------------------------------
#define SM_Q   0        // Qhi 8192, Qlo 8192
#define SM_K   16384    // + b*8192 : Khi 4096 | Klo 4096   (b = 0,1)
#define SM_V   32768    // + b*8192 : Vhi 4096 | Vlo 4096   (b = 0..2)
#define SM_P   57344    // + b*8192 : Phi 4096 | Plo 4096   (b = 0,1) 64 rows x 64B
#define SM_L   16384    // lsum[64] floats (reuses K after loops)
#define SM_BYTES 73728

__global__ __launch_bounds__(256, 2) void attn_kernel(float* __restrict__ O) {
    extern __shared__ __align__(1024) char smem[];
    const uint32_t sb = smem_u32(smem);
    const int tid  = threadIdx.x;
    const int lane = tid & 31;
    const int warp = tid >> 5;
    const bool isQK = warp < 4;
    const int w    = warp & 3;            // row-group (16 rows) within role
    const int qt   = 31 - blockIdx.x;
    const int bh   = blockIdx.y;
    const size_t hoff = (size_t)bh * S_LEN * DH;
    const int nt   = 2 * qt + 2;

    const int r0g = qt * 64 + 16 * w + (lane >> 2);
    const int cb0 = 2 * (lane & 3);

    if (isQK) {
        // ================= QK + softmax warps =================
        const int t128 = tid;   // 0..127
        // K tile loader: 512 chunks (Khi 256 + Klo 256), 4 per thread
        auto kload = [&](int t) {
            const uint32_t kb = sb + SM_K + (uint32_t)(t & 1) * 8192;
            const char* sh = (const char*)(g_Khi + hoff) + (size_t)t * 32 * 128;
            const char* sl = (const char*)(g_Klo + hoff) + (size_t)t * 32 * 128;
#pragma unroll
            for (int k = 0; k < 4; k++) {
                int id = t128 + 128 * k;
                int arr = id >> 8, q = id & 255;
                int r = q >> 3, c = q & 7;
                cp16(kb + (uint32_t)(arr * 4096 + r * 128 + (((c << 4)) ^ ((r & 7) << 4))),
                     (arr ? sl : sh) + r * 128 + c * 16);
            }
        };
        // prologue: Q (8 chunks/thread) then K0
        {
            const char* gQh = (const char*)(g_Qhi + hoff) + (size_t)qt * 64 * 128;
            const char* gQl = (const char*)(g_Qlo + hoff) + (size_t)qt * 64 * 128;
#pragma unroll
            for (int k = 0; k < 8; k++) {
                int id = t128 + 128 * k;            // 0..1023
                int arr = id >> 9, q = id & 511;
                int r = q >> 3, c = q & 7;
                cp16(sb + SM_Q + (uint32_t)(arr * 8192 + r * 128 + ((c << 4) ^ ((r & 7) << 4))),
                     (arr ? gQl : gQh) + r * 128 + c * 16);
            }
            cp_commit();
            kload(0);
            cp_commit();
            cp_wait<0>();
            BAR_SYNC(7, 128);
        }

        // hoist Q fragments (rows 16w..16w+15)
        const int ar  = 16 * w + (lane & 15);
        const int acs = ((lane >> 4) & 1) << 4;
        const uint32_t asw = (uint32_t)((ar & 7) << 4);
        uint32_t qh[4][4], ql[4][4];
#pragma unroll
        for (int kc = 0; kc < 4; kc++) {
            const uint32_t aoff = (uint32_t)(((kc << 5) | acs) ^ asw);
            ldsm4(qh[kc], sb + SM_Q        + (uint32_t)(ar * 128) + aoff);
            ldsm4(ql[kc], sb + SM_Q + 8192 + (uint32_t)(ar * 128) + aoff);
        }

        // K B-frag addressing (BN=32: 2 n-pairs)
        const int ki = lane >> 3, kr = lane & 7;
        const uint32_t krow_off  = (uint32_t)(((ki >> 1) * 8 + kr) * 128);
        const uint32_t khalf_sel = (uint32_t)((ki & 1) << 4);
        const uint32_t krsw      = (uint32_t)(kr << 4);
        // P store addressing
        const int pr0 = 16 * w + (lane >> 2);       // row of (e0,e1); +8 for (e2,e3)
        float lsum0 = 0.0f, lsum1 = 0.0f;

        for (int i = 0; i < nt; i++) {
            cp_wait<0>();           // K(i) landed (issued last iter / prologue)
            BAR_SYNC(7, 128);       // K(i) visible to all QK warps
            if (i + 1 < nt) { kload(i + 1); cp_commit(); }   // overlaps compute
            if (i >= 2) BAR_SYNC(3 + (i & 1), 256);          // P buf (i&1) free

            const bool skip = (32 * i > qt * 64 + 16 * w + 15);
            if (!skip) {
                const uint32_t kvb = sb + SM_K + (uint32_t)(i & 1) * 8192;
                const uint32_t pb  = sb + SM_P + (uint32_t)(i & 1) * 8192;
                const bool unmasked = (32 * i + 31 <= qt * 64 + 16 * w);
#pragma unroll
                for (int jp = 0; jp < 2; jp++) {
                    float c0[4] = {0.f, 0.f, 0.f, 0.f};
                    float c1[4] = {0.f, 0.f, 0.f, 0.f};
                    const uint32_t kbase = (uint32_t)(jp << 11) + krow_off;
#pragma unroll
                    for (int kc = 0; kc < 4; kc++) {
                        uint32_t k4h[4], k4l[4];
                        const uint32_t kb_ = kbase + ((((uint32_t)(kc << 5)) | khalf_sel) ^ krsw);
                        ldsm4(k4h, kvb + kb_);
                        ldsm4(k4l, kvb + 4096 + kb_);
                        mma_bf16(c0, qh[kc], k4h[0], k4h[1]);
                        mma_bf16(c1, qh[kc], k4h[2], k4h[3]);
                        mma_bf16(c0, qh[kc], k4l[0], k4l[1]);
                        mma_bf16(c1, qh[kc], k4l[2], k4l[3]);
                        mma_bf16(c0, ql[kc], k4h[0], k4h[1]);
                        mma_bf16(c1, ql[kc], k4h[2], k4h[3]);
                    }
                    float e0, e1, e2, e3, f0, f1, f2, f3;
                    if (unmasked) {
                        e0 = ex2(c0[0]); e1 = ex2(c0[1]); e2 = ex2(c0[2]); e3 = ex2(c0[3]);
                        f0 = ex2(c1[0]); f1 = ex2(c1[1]); f2 = ex2(c1[2]); f3 = ex2(c1[3]);
                    } else {
                        const int cj0 = 32 * i + 16 * jp + cb0, cj1 = cj0 + 8;
                        e0 = (cj0     <= r0g)     ? ex2(c0[0]) : 0.0f;
                        e1 = (cj0 + 1 <= r0g)     ? ex2(c0[1]) : 0.0f;
                        e2 = (cj0     <= r0g + 8) ? ex2(c0[2]) : 0.0f;
                        e3 = (cj0 + 1 <= r0g + 8) ? ex2(c0[3]) : 0.0f;
                        f0 = (cj1     <= r0g)     ? ex2(c1[0]) : 0.0f;
                        f1 = (cj1 + 1 <= r0g)     ? ex2(c1[1]) : 0.0f;
                        f2 = (cj1     <= r0g + 8) ? ex2(c1[2]) : 0.0f;
                        f3 = (cj1 + 1 <= r0g + 8) ? ex2(c1[3]) : 0.0f;
                    }
                    lsum0 += (e0 + e1) + (f0 + f1);
                    lsum1 += (e2 + e3) + (f2 + f3);

                    // store P pairs: n-tile j at chunk j with swizzle (row>>1)&3
                    uint32_t h, l;
                    const int j0 = 2 * jp, j1 = 2 * jp + 1;
                    const uint32_t bofs = (uint32_t)(4 * (lane & 3));
                    uint32_t a0 = pb + (uint32_t)(pr0 * 64 + 16 * (j0 ^ ((pr0 >> 1) & 3))) + bofs;
                    uint32_t a1 = pb + (uint32_t)((pr0 + 8) * 64 + 16 * (j0 ^ (((pr0 + 8) >> 1) & 3))) + bofs;
                    uint32_t a2 = pb + (uint32_t)(pr0 * 64 + 16 * (j1 ^ ((pr0 >> 1) & 3))) + bofs;
                    uint32_t a3 = pb + (uint32_t)((pr0 + 8) * 64 + 16 * (j1 ^ (((pr0 + 8) >> 1) & 3))) + bofs;
                    pack_pair(e0, e1, h, l);
                    asm volatile("st.shared.b32 [%0], %1;" :: "r"(a0), "r"(h) : "memory");
                    asm volatile("st.shared.b32 [%0], %1;" :: "r"(a0 + 4096), "r"(l) : "memory");
                    pack_pair(e2, e3, h, l);
                    asm volatile("st.shared.b32 [%0], %1;" :: "r"(a1), "r"(h) : "memory");
                    asm volatile("st.shared.b32 [%0], %1;" :: "r"(a1 + 4096), "r"(l) : "memory");
                    pack_pair(f0, f1, h, l);
                    asm volatile("st.shared.b32 [%0], %1;" :: "r"(a2), "r"(h) : "memory");
                    asm volatile("st.shared.b32 [%0], %1;" :: "r"(a2 + 4096), "r"(l) : "memory");
                    pack_pair(f2, f3, h, l);
                    asm volatile("st.shared.b32 [%0], %1;" :: "r"(a3), "r"(h) : "memory");
                    asm volatile("st.shared.b32 [%0], %1;" :: "r"(a3 + 4096), "r"(l) : "memory");
                }
            }
            BAR_ARRIVE(1 + (i & 1), 256);   // P(i) ready
            BAR_SYNC(5, 128);               // all QK done reading K(i)
        }

        // lsum handoff
        lsum0 += __shfl_xor_sync(0xffffffffu, lsum0, 1);
        lsum0 += __shfl_xor_sync(0xffffffffu, lsum0, 2);
        lsum1 += __shfl_xor_sync(0xffffffffu, lsum1, 1);
        lsum1 += __shfl_xor_sync(0xffffffffu, lsum1, 2);
        if ((lane & 3) == 0) {
            const int rr = 16 * w + (lane >> 2);
            asm volatile("st.shared.f32 [%0], %1;" :: "r"(sb + SM_L + rr * 4), "f"(lsum0) : "memory");
            asm volatile("st.shared.f32 [%0], %1;" :: "r"(sb + SM_L + (rr + 8) * 4), "f"(lsum1) : "memory");
        }
        __syncthreads();
    } else {
        // ================= PV warps =================
        const int t128 = tid - 128;
        auto vload = [&](int t) {
            const uint32_t vb = sb + SM_V + (uint32_t)(t % 3) * 8192;
            const char* sh = (const char*)(g_Vhi + hoff) + (size_t)t * 32 * 128;
            const char* sl = (const char*)(g_Vlo + hoff) + (size_t)t * 32 * 128;
#pragma unroll
            for (int k = 0; k < 4; k++) {
                int id = t128 + 128 * k;
                int arr = id >> 8, q = id & 255;
                int r = q >> 3, c = q & 7;
                cp16(vb + (uint32_t)(arr * 4096 + r * 128 + ((c << 4) ^ ((r & 7) << 4))),
                     (arr ? sl : sh) + r * 128 + c * 16);
            }
        };
        vload(0); cp_commit();
        if (nt > 1) { vload(1); cp_commit(); }

        // P A-frag addressing
        const int prow = 16 * w + (lane & 15);
        const uint32_t pbase = (uint32_t)(prow * 64);
        const uint32_t pswz  = (uint32_t)((prow >> 1) & 3);
        const uint32_t csel  = (uint32_t)(lane >> 4);
        // V B-frag addressing
        const int vi = lane >> 3, vr = lane & 7;
        const uint32_t vrow_off = (uint32_t)(((vi & 1) * 8 + vr) * 128);
        const uint32_t vdsel    = (uint32_t)(vi >> 1);
        const uint32_t vrsw     = (uint32_t)(vr << 4);

        float o[8][4];
#pragma unroll
        for (int j = 0; j < 8; j++)
#pragma unroll
            for (int e = 0; e < 4; e++) o[j][e] = 0.0f;

        for (int j = 0; j < nt; j++) {
            if (j + 2 < nt) cp_wait<1>(); else cp_wait<0>();
            BAR_SYNC(8, 128);               // V(j) visible to all PV warps
            if (j + 2 < nt) { vload(j + 2); cp_commit(); }
            BAR_SYNC(1 + (j & 1), 256);     // P(j) ready

            const bool skip = (32 * j > qt * 64 + 16 * w + 15);
            if (!skip) {
                const uint32_t vb = sb + SM_V + (uint32_t)(j % 3) * 8192;
                const uint32_t pb = sb + SM_P + (uint32_t)(j & 1) * 8192;
#pragma unroll
                for (int kc = 0; kc < 2; kc++) {
                    uint32_t Ph[4], Pl[4];
                    const uint32_t pa = pb + pbase + 16u * (((uint32_t)(2 * kc) + csel) ^ pswz);
                    ldsm4(Ph, pa);
                    ldsm4(Pl, pa + 4096);
                    const uint32_t kcrow = (uint32_t)(kc << 11) + vrow_off;
#pragma unroll
                    for (int dp = 0; dp < 4; dp++) {
                        uint32_t v4h[4], v4l[4];
                        const uint32_t va = kcrow + ((((uint32_t)(2 * dp) + vdsel) << 4) ^ vrsw);
                        ldsm4t(v4h, vb + va);
                        ldsm4t(v4l, vb + 4096 + va);
                        mma_bf16(o[2 * dp],     Ph, v4h[0], v4h[1]);
                        mma_bf16(o[2 * dp + 1], Ph, v4h[2], v4h[3]);
                        mma_bf16(o[2 * dp],     Ph, v4l[0], v4l[1]);
                        mma_bf16(o[2 * dp + 1], Ph, v4l[2], v4l[3]);
                        mma_bf16(o[2 * dp],     Pl, v4h[0], v4h[1]);
                        mma_bf16(o[2 * dp + 1], Pl, v4h[2], v4h[3]);
                    }
                }
            }
            BAR_ARRIVE(3 + (j & 1), 256);   // P buf (j&1) free
            BAR_SYNC(9, 128);               // all PV done reading V(j)
        }

        __syncthreads();                    // lsum published by QK warps
        float l0, l1;
        const int rr = 16 * w + (lane >> 2);
        asm volatile("ld.shared.f32 %0, [%1];" : "=f"(l0) : "r"(sb + SM_L + rr * 4));
        asm volatile("ld.shared.f32 %0, [%1];" : "=f"(l1) : "r"(sb + SM_L + (rr + 8) * 4));
        const float inv0 = 1.0f / l0;
        const float inv1 = 1.0f / l1;
        float* ob0 = O + hoff + (size_t)r0g * DH;
        float* ob1 = ob0 + 8 * DH;
#pragma unroll
        for (int j = 0; j < 8; j++) {
            float2 w0 = {o[j][0] * inv0, o[j][1] * inv0};
            float2 w1 = {o[j][2] * inv1, o[j][3] * inv1};
            *(float2*)&ob0[j * 8 + cb0] = w0;
            *(float2*)&ob1[j * 8 + cb0] = w1;
        }
    }
}

// ---------------------------------------------------------------------------
extern "C" void kernel_launch(void* const* d_in, const int* in_sizes, int n_in,
                              void* d_out, int out_size) {
    const float* Q = (const float*)d_in[0];
    const float* K = (const float*)d_in[1];
    const float* V = (const float*)d_in[2];
    float* O = (float*)d_out;

    int pairs = in_sizes[0] / 2;
    prep_kernel<<<(pairs + 255) / 256, 256>>>(Q, K, V, pairs);

    cudaFuncSetAttribute(attn_kernel, cudaFuncAttributeMaxDynamicSharedMemorySize, SM_BYTES);
    attn_kernel<<<dim3(32, 32), 256, SM_BYTES>>>(O);
}